// round 1
// baseline (speedup 1.0000x reference)
#include <cuda_runtime.h>

#define NB   1024     // codebook size
#define CD   512      // code dim
#define NN   32       // batch
#define TD   2048     // time
#define NT   (NN*TD)  // 65536 vectors
#define TT   64       // t-tile per block
#define NBLK (NT/TT)  // 1024 blocks

typedef unsigned long long ull;

// scratch (allowed: __device__ globals, no allocation)
__device__ float g_cbnorm[NB];
__device__ int   g_counts[NB];
__device__ float g_partials[NBLK];

static __device__ __forceinline__ ull ffma2(ull a, ull b, ull c){
    ull d; asm("fma.rn.f32x2 %0, %1, %2, %3;" : "=l"(d) : "l"(a), "l"(b), "l"(c)); return d;
}
static __device__ __forceinline__ float lo32(ull v){ return __uint_as_float((unsigned)v); }
static __device__ __forceinline__ float hi32(ull v){ return __uint_as_float((unsigned)(v>>32)); }
static __device__ __forceinline__ ull dup2(float v){ unsigned b = __float_as_uint(v); return (((ull)b)<<32)|b; }

// ---------------- kernel 0: codebook norms + zero counts ----------------
__global__ void k_norms(const float* __restrict__ cb){
    int j = blockIdx.x;
    float s = 0.f;
    for (int c = threadIdx.x; c < CD; c += 128){
        float v = cb[(size_t)j*CD + c]; s = fmaf(v, v, s);
    }
    #pragma unroll
    for (int o = 16; o; o >>= 1) s += __shfl_xor_sync(~0u, s, o);
    __shared__ float ws[4];
    if ((threadIdx.x & 31) == 0) ws[threadIdx.x >> 5] = s;
    __syncthreads();
    if (threadIdx.x == 0){
        g_cbnorm[j] = (ws[0] + ws[1]) + (ws[2] + ws[3]);
        g_counts[j] = 0;
    }
}

// ---------------- kernel 1: main GEMM + argmin + gather + commit ----------------
// smem layout (bytes)
#define SM_XS      0                       // float xs[512*64]            = 131072
#define SM_CBN     131072                  // float cbn[1024]             = 4096
#define SM_XNORM   135168                  // float xnorm[64]             = 256
#define SM_XPART   135424                  // float xpart[2*64]           = 512
#define SM_IDXS    135936                  // int   idxS[64]              = 256
#define SM_WRED    136192                  // float wred[8]               = 32
#define SM_SCR     136224                  // union: cbt(64*33 ull2=33792) / sred(8192) / qt(8448)
#define SM_TOTAL   (SM_SCR + 64*33*16)     // 170016

__global__ __launch_bounds__(128, 1)
void k_main(const float* __restrict__ x, const float* __restrict__ cb, float* __restrict__ out){
    extern __shared__ char smem[];
    float* xs     = (float*)(smem + SM_XS);
    float* cbn    = (float*)(smem + SM_CBN);
    float* xnorm  = (float*)(smem + SM_XNORM);
    float* xpart  = (float*)(smem + SM_XPART);
    int*   idxS   = (int*)  (smem + SM_IDXS);
    float* wred   = (float*)(smem + SM_WRED);
    ulonglong2* cbt2 = (ulonglong2*)(smem + SM_SCR);
    ull*        cbtU = (ull*)       (smem + SM_SCR);
    float2*     sred = (float2*)    (smem + SM_SCR);
    float*      qt   = (float*)     (smem + SM_SCR);

    const int tid = threadIdx.x;
    const int tx  = tid & 15;   // 16 j-groups (4 j each)
    const int ty  = tid >> 4;   // 8 t-groups (8 t each)
    const int bx  = blockIdx.x;
    const int n   = bx >> 5;
    const int t0  = (bx & 31) * TT;
    const float* xblk = x + (size_t)n*CD*TD + t0;

    // load x tile: xs[c*64 + t], coalesced float4 along t
    {
        float4* xs4 = (float4*)xs;
        for (int i = tid; i < CD*16; i += 128){
            int c = i >> 4, q = i & 15;
            xs4[i] = *(const float4*)(xblk + (size_t)c*TD + q*4);
        }
    }
    for (int i = tid; i < NB; i += 128) cbn[i] = g_cbnorm[i];
    __syncthreads();

    // x norms (||x_t||^2)
    {
        int t = tid & 63, h = tid >> 6;
        float s = 0.f;
        int c0 = h * 256;
        for (int c = c0; c < c0 + 256; ++c){ float v = xs[c*64 + t]; s = fmaf(v, v, s); }
        xpart[h*64 + t] = s;
    }
    __syncthreads();
    if (tid < 64) xnorm[tid] = xpart[tid] + xpart[64 + tid];
    __syncthreads();

    float bestd[8]; int bestj[8];
    #pragma unroll
    for (int i = 0; i < 8; ++i){ bestd[i] = 3.4e38f; bestj[i] = 0; }

    const ulonglong2* xs2 = (const ulonglong2*)xs;

    for (int jt = 0; jt < 16; ++jt){
        ull acc[4][4];
        #pragma unroll
        for (int a = 0; a < 4; ++a)
            #pragma unroll
            for (int b = 0; b < 4; ++b) acc[a][b] = 0ULL;

        for (int cc = 0; cc < 8; ++cc){            // 8 chunks of 64 c
            __syncthreads();
            // stage codebook chunk, duplicated f32x2, split-half layout:
            // ull2 slot (c*33 + h*16 + (j>>2)) holds j=4*(j>>2)+2h (+0 in .x, +1 in .y), each dup'd
            {
                int c  = tid & 63;
                int jr = tid >> 6;                 // 0..1
                const float* src = cb + (size_t)(jt*64 + jr)*CD + cc*64 + c;
                #pragma unroll
                for (int p = 0; p < 32; ++p){
                    int j = p*2 + jr;
                    float v = src[(size_t)p*2*CD];
                    int h = (j >> 1) & 1, r = j & 1;
                    cbtU[(((c*33) + h*16 + (j >> 2)) << 1) | r] = dup2(v);
                }
            }
            __syncthreads();
            #pragma unroll 4
            for (int c = 0; c < 64; ++c){
                int ca = cc*64 + c;
                ulonglong2 xa  = xs2[ca*16 + ty*2];
                ulonglong2 xb  = xs2[ca*16 + ty*2 + 1];
                ulonglong2 blo = cbt2[c*33 + tx];
                ulonglong2 bhi = cbt2[c*33 + 16 + tx];
                acc[0][0] = ffma2(blo.x, xa.x, acc[0][0]);
                acc[0][1] = ffma2(blo.x, xa.y, acc[0][1]);
                acc[0][2] = ffma2(blo.x, xb.x, acc[0][2]);
                acc[0][3] = ffma2(blo.x, xb.y, acc[0][3]);
                acc[1][0] = ffma2(blo.y, xa.x, acc[1][0]);
                acc[1][1] = ffma2(blo.y, xa.y, acc[1][1]);
                acc[1][2] = ffma2(blo.y, xb.x, acc[1][2]);
                acc[1][3] = ffma2(blo.y, xb.y, acc[1][3]);
                acc[2][0] = ffma2(bhi.x, xa.x, acc[2][0]);
                acc[2][1] = ffma2(bhi.x, xa.y, acc[2][1]);
                acc[2][2] = ffma2(bhi.x, xb.x, acc[2][2]);
                acc[2][3] = ffma2(bhi.x, xb.y, acc[2][3]);
                acc[3][0] = ffma2(bhi.y, xa.x, acc[3][0]);
                acc[3][1] = ffma2(bhi.y, xa.y, acc[3][1]);
                acc[3][2] = ffma2(bhi.y, xb.x, acc[3][2]);
                acc[3][3] = ffma2(bhi.y, xb.y, acc[3][3]);
            }
        }
        // finalize this j-tile: dist = (||x||^2 - 2*dot) + ||k||^2, mimic ref rounding
        #pragma unroll
        for (int jj = 0; jj < 4; ++jj){
            int j = jt*64 + tx*4 + jj;
            float cn = cbn[j];
            #pragma unroll
            for (int p = 0; p < 4; ++p){
                float d0 = __fadd_rn(__fsub_rn(xnorm[ty*8 + p*2],     2.f*lo32(acc[jj][p])), cn);
                float d1 = __fadd_rn(__fsub_rn(xnorm[ty*8 + p*2 + 1], 2.f*hi32(acc[jj][p])), cn);
                if (d0 < bestd[p*2])     { bestd[p*2]     = d0; bestj[p*2]     = j; }
                if (d1 < bestd[p*2 + 1]) { bestd[p*2 + 1] = d1; bestj[p*2 + 1] = j; }
            }
        }
    }

    // cross-thread argmin reduce (first-min tie-break => smaller index on equal dist)
    __syncthreads();
    #pragma unroll
    for (int i = 0; i < 8; ++i){
        int t = ty*8 + i;
        sred[t*16 + tx] = make_float2(bestd[i], __int_as_float(bestj[i]));
    }
    __syncthreads();
    if (tid < 64){
        float bd = 3.4e38f; int bj = 0x7fffffff;
        #pragma unroll
        for (int k = 0; k < 16; ++k){
            float2 e = sred[tid*16 + k];
            int j = __float_as_int(e.y);
            if (e.x < bd || (e.x == bd && j < bj)){ bd = e.x; bj = j; }
        }
        idxS[tid] = bj;
        atomicAdd(&g_counts[bj], 1);
    }

    // epilogue: gather q = codebook[idx], write straight-through output, commit partial
    float csum = 0.f;
    float* outblk = out + (size_t)n*CD*TD + t0;
    for (int ch = 0; ch < 16; ++ch){       // 16 chunks of 32 c
        __syncthreads();                   // qt (scratch) reuse guard
        {
            int c  = tid & 31;
            int tr = tid >> 5;             // 0..3
            #pragma unroll
            for (int p = 0; p < 16; ++p){
                int t = p*4 + tr;
                qt[t*33 + c] = cb[(size_t)idxS[t]*CD + ch*32 + c];   // coalesced row read
            }
        }
        __syncthreads();
        {
            int t  = tid & 63;
            int cr = tid >> 6;             // 0..1
            #pragma unroll
            for (int p = 0; p < 16; ++p){
                int c  = p*2 + cr;
                float q  = qt[t*33 + c];
                float xv = xs[(ch*32 + c)*64 + t];
                outblk[(size_t)(ch*32 + c)*TD + t] = __fadd_rn(xv, __fsub_rn(q, xv));
                float df = __fsub_rn(xv, q);
                csum = fmaf(df, df, csum);
            }
        }
    }
    // deterministic block commit reduce
    #pragma unroll
    for (int o = 16; o; o >>= 1) csum += __shfl_xor_sync(~0u, csum, o);
    __syncthreads();
    if ((tid & 31) == 0) wred[tid >> 5] = csum;
    __syncthreads();
    if (tid == 0) g_partials[blockIdx.x] = (wred[0] + wred[1]) + (wred[2] + wred[3]);
}

// ---------------- kernel 2: finalize commit loss + perplexity ----------------
__global__ void k_final(float* __restrict__ out){
    __shared__ double sd[256];
    int tid = threadIdx.x;
    double s = 0.0;
    for (int i = tid; i < NBLK; i += 256) s += (double)g_partials[i];
    sd[tid] = s; __syncthreads();
    for (int o = 128; o; o >>= 1){ if (tid < o) sd[tid] += sd[tid + o]; __syncthreads(); }
    double commit = sd[0] / ((double)NT * (double)CD);
    __syncthreads();
    double e = 0.0;
    for (int i = tid; i < NB; i += 256){
        double p = (double)g_counts[i] / (double)NT;
        e += p * log(p + 1e-7);
    }
    sd[tid] = e; __syncthreads();
    for (int o = 128; o; o >>= 1){ if (tid < o) sd[tid] += sd[tid + o]; __syncthreads(); }
    if (tid == 0){
        out[(size_t)NN*CD*TD]     = (float)commit;
        out[(size_t)NN*CD*TD + 1] = (float)exp(-sd[0]);
    }
}

extern "C" void kernel_launch(void* const* d_in, const int* in_sizes, int n_in,
                              void* d_out, int out_size){
    const float* x  = (const float*)d_in[0];   // (32, 512, 2048) fp32
    const float* cb = (const float*)d_in[1];   // (1024, 512) fp32
    float* out = (float*)d_out;                // NCT floats + commit + perplexity

    cudaFuncSetAttribute(k_main, cudaFuncAttributeMaxDynamicSharedMemorySize, SM_TOTAL);

    k_norms<<<NB, 128>>>(cb);
    k_main<<<NBLK, 128, SM_TOTAL>>>(x, cb, out);
    k_final<<<1, 256>>>(out);
}

// round 4
// speedup vs baseline: 3.9395x; 3.9395x over previous
#include <cuda_runtime.h>
#include <cuda_bf16.h>
#include <cstdint>

#define NB   1024
#define CD   512
#define NN   32
#define TD   2048
#define NT   (NN*TD)      // 65536 rows
#define MT   128          // rows per CTA
#define NTILE (NT/MT)     // 512 CTAs
#define PASSES 8
#define PN   128          // codes per pass
#define KC   128          // k per chunk
#define NCH  4            // chunks per pass
#define CHT  (PASSES*NCH) // 32 chunks total
#define MARGIN 1.5f
#define CMAX 8

typedef unsigned long long ull;

__device__ __align__(16) __nv_bfloat16 g_cb16[NB*CD];
__device__ float g_cbnorm[NB];
__device__ int   g_counts[NB];
__device__ float g_partials[NTILE];
__device__ int   g_idx[NT];

// smem map (bytes): A 128x512 bf16 swizzled @0 (131072), B 2x32768 @131072 (cand overlay 49152), cbn @196608 (4096)
#define SA    0
#define SB    131072
#define SCBN  196608
#define SMTOT 200704

static __device__ __forceinline__ uint32_t smem_u32(const void* p){
    uint32_t a; asm("{ .reg .u64 t; cvta.to.shared.u64 t, %1; cvt.u32.u64 %0, t; }" : "=r"(a) : "l"(p));
    return a;
}
static __device__ __forceinline__ uint32_t A_off(int r, int c){
    int ck = c >> 3;
    int cks = (ck & ~7) | ((ck ^ r) & 7);
    return (uint32_t)(r*1024 + cks*16 + (c&7)*2);
}
static __device__ __forceinline__ uint32_t B_off(int j, int kk){
    int ck = kk >> 3;
    int cks = (ck & 8) | ((ck ^ j) & 7);
    return (uint32_t)(j*256 + cks*16 + (kk&7)*2);
}
static __device__ __forceinline__ void ldsm4(uint32_t* r, uint32_t addr){
    asm volatile("ldmatrix.sync.aligned.m8n8.x4.shared.b16 {%0,%1,%2,%3}, [%4];"
        : "=r"(r[0]), "=r"(r[1]), "=r"(r[2]), "=r"(r[3]) : "r"(addr));
}
static __device__ __forceinline__ void mma16816(float* c, const uint32_t* a, uint32_t b0, uint32_t b1){
    asm volatile("mma.sync.aligned.m16n8k16.row.col.f32.bf16.bf16.f32 "
        "{%0,%1,%2,%3}, {%4,%5,%6,%7}, {%8,%9}, {%0,%1,%2,%3};"
        : "+f"(c[0]), "+f"(c[1]), "+f"(c[2]), "+f"(c[3])
        : "r"(a[0]), "r"(a[1]), "r"(a[2]), "r"(a[3]), "r"(b0), "r"(b1));
}

// ---------------- kernel 0: codebook norms + bf16 convert + zero counts ----------------
__global__ void k_norms(const float* __restrict__ cb){
    int j = blockIdx.x;
    float s = 0.f;
    for (int c = threadIdx.x; c < CD; c += 128){
        float v = cb[(size_t)j*CD + c];
        g_cb16[(size_t)j*CD + c] = __float2bfloat16(v);
        s = fmaf(v, v, s);
    }
    #pragma unroll
    for (int o = 16; o; o >>= 1) s += __shfl_xor_sync(~0u, s, o);
    __shared__ float ws[4];
    if ((threadIdx.x & 31) == 0) ws[threadIdx.x >> 5] = s;
    __syncthreads();
    if (threadIdx.x == 0){
        g_cbnorm[j] = (ws[0] + ws[1]) + (ws[2] + ws[3]);
        g_counts[j] = 0;
    }
}

// ---------------- B chunk stage via cp.async ----------------
static __device__ __forceinline__ void issueB(int q, int tid, uint32_t sbase){
    int p = q >> 2, kc = q & 3;
    const __nv_bfloat16* src0 = g_cb16 + (size_t)p*PN*CD + kc*KC;
    uint32_t bufb = sbase + SB + (uint32_t)(q & 1)*32768u;
    #pragma unroll
    for (int it = 0; it < 8; ++it){
        int idx = tid + it*256;
        int j = idx >> 4, ck = idx & 15;
        uint32_t dst = bufb + (uint32_t)(j*256 + (((ck & 8) | ((ck ^ j) & 7)) << 4));
        const void* srcp = (const void*)(src0 + (size_t)j*CD + ck*8);
        asm volatile("cp.async.cg.shared.global [%0], [%1], 16;" :: "r"(dst), "l"(srcp));
    }
    asm volatile("cp.async.commit_group;");
}

// ---------------- kernel 1: bf16 mma.sync GEMM + top3 + exact refine ----------------
__global__ __launch_bounds__(256, 1)
void k_main(const float* __restrict__ x, const float* __restrict__ cb){
    extern __shared__ char sm[];
    const uint32_t sbase = smem_u32(sm);
    const int tid = threadIdx.x;
    const int wid = tid >> 5, l = tid & 31;
    const int wm = wid >> 2, wn = wid & 3;        // 2 M-warps x 4 N-warps
    const int b = blockIdx.x, n = b >> 4, t0 = (b & 15) * MT;
    const float* xblk = x + (size_t)n*CD*TD + t0;
    float* cbn_s = (float*)(sm + SCBN);

    for (int i = tid; i < NB; i += 256) cbn_s[i] = g_cbnorm[i];

    // ---- stage A: x tile -> bf16, swizzled [t][c] ----
    #pragma unroll 4
    for (int it = 0; it < 128; ++it){
        int idx = tid + it*256;
        int t = idx & 127, c = (idx >> 7) * 2;
        float v0 = xblk[(size_t)c*TD + t];
        float v1 = xblk[(size_t)(c+1)*TD + t];
        __nv_bfloat162 pk = __floats2bfloat162_rn(v0, v1);
        *(__nv_bfloat162*)(sm + SA + A_off(t, c)) = pk;
    }
    __syncthreads();

    issueB(0, tid, sbase);

    float bd[8][3]; int bjv[8][3];
    #pragma unroll
    for (int r = 0; r < 8; ++r)
        #pragma unroll
        for (int s = 0; s < 3; ++s){ bd[r][s] = 3.4e38f; bjv[r][s] = 0; }

    for (int p = 0; p < PASSES; ++p){
        float acc[4][4][4];
        #pragma unroll
        for (int ti = 0; ti < 4; ++ti)
            #pragma unroll
            for (int tj = 0; tj < 4; ++tj)
                #pragma unroll
                for (int e = 0; e < 4; ++e) acc[ti][tj][e] = 0.f;

        for (int kc = 0; kc < NCH; ++kc){
            int q = p*NCH + kc;
            if (q + 1 < CHT){ issueB(q + 1, tid, sbase); asm volatile("cp.async.wait_group 1;"); }
            else            { asm volatile("cp.async.wait_group 0;"); }
            __syncthreads();
            uint32_t bufb = sbase + SB + (uint32_t)(q & 1)*32768u;

            const int arow = wm*64 + ((l >> 3) & 1)*8 + (l & 7);
            const int brow = wn*32 + (l >> 4)*8 + (l & 7);
            #pragma unroll
            for (int ks = 0; ks < 8; ++ks){
                const int acol = kc*KC + ks*16 + (l >> 4)*8;
                const int bcol = ks*16 + ((l >> 3) & 1)*8;
                uint32_t a[4][4], bf[2][4];
                #pragma unroll
                for (int ti = 0; ti < 4; ++ti)
                    ldsm4(a[ti], sbase + SA + A_off(arow + ti*16, acol));
                #pragma unroll
                for (int pr = 0; pr < 2; ++pr)
                    ldsm4(bf[pr], bufb + B_off(brow + pr*16, bcol));
                #pragma unroll
                for (int ti = 0; ti < 4; ++ti)
                    #pragma unroll
                    for (int tj = 0; tj < 4; ++tj)
                        mma16816(acc[ti][tj], a[ti], bf[tj>>1][(tj&1)*2], bf[tj>>1][(tj&1)*2+1]);
            }
            __syncthreads();
        }
        // ---- pass epilogue: distances -> thread-local top3 ----
        #pragma unroll
        for (int ti = 0; ti < 4; ++ti)
            #pragma unroll
            for (int tj = 0; tj < 4; ++tj)
                #pragma unroll
                for (int e = 0; e < 4; ++e){
                    int jg = p*PN + wn*32 + tj*8 + (l & 3)*2 + (e & 1);
                    float d = fmaf(-2.f, acc[ti][tj][e], cbn_s[jg]);
                    int r = ti*2 + (e >> 1);
                    if (d < bd[r][0]){
                        bd[r][2]=bd[r][1]; bjv[r][2]=bjv[r][1];
                        bd[r][1]=bd[r][0]; bjv[r][1]=bjv[r][0];
                        bd[r][0]=d;        bjv[r][0]=jg;
                    } else if (d < bd[r][1]){
                        bd[r][2]=bd[r][1]; bjv[r][2]=bjv[r][1];
                        bd[r][1]=d;        bjv[r][1]=jg;
                    } else if (d < bd[r][2]){
                        bd[r][2]=d;        bjv[r][2]=jg;
                    }
                }
    }

    // ---- dump candidates (overlay B buffers): cand[128][4 wn][4 lane][3] of (d, j) ----
    float2* cand = (float2*)(sm + SB);
    #pragma unroll
    for (int r = 0; r < 8; ++r){
        int m = wm*64 + (r >> 1)*16 + (r & 1)*8 + (l >> 2);
        #pragma unroll
        for (int s = 0; s < 3; ++s)
            cand[m*48 + wn*12 + (l & 3)*3 + s] = make_float2(bd[r][s], __int_as_float(bjv[r][s]));
    }
    __syncthreads();

    // ---- per-row pick + exact fp32 refine if margin small ----
    if (tid < MT){
        int m = tid;
        float b1 = 3.4e38f; int j1 = 0x7fffffff;
        #pragma unroll 4
        for (int s = 0; s < 48; ++s){
            float2 e = cand[m*48 + s];
            int j = __float_as_int(e.y);
            if (e.x < b1 || (e.x == b1 && j < j1)){ b1 = e.x; j1 = j; }
        }
        int cj[CMAX]; int ncand = 0;
        #pragma unroll 4
        for (int s = 0; s < 48; ++s){
            float2 e = cand[m*48 + s];
            if (e.x <= b1 + MARGIN && ncand < CMAX) cj[ncand++] = __float_as_int(e.y);
        }
        int jf = j1;
        if (ncand > 1){
            float sacc[CMAX];
            const float* cps[CMAX];
            #pragma unroll
            for (int q2 = 0; q2 < CMAX; ++q2){
                sacc[q2] = 0.f;
                cps[q2] = cb + (size_t)cj[q2 < ncand ? q2 : 0]*CD;
            }
            const float* xr = xblk + m;
            #pragma unroll 4
            for (int c = 0; c < CD; ++c){
                float xv = xr[(size_t)c*TD];
                #pragma unroll
                for (int q2 = 0; q2 < CMAX; ++q2)
                    if (q2 < ncand) sacc[q2] = fmaf(xv, cps[q2][c], sacc[q2]);
            }
            float bdx = 3.4e38f; jf = 0x7fffffff;
            #pragma unroll
            for (int q2 = 0; q2 < CMAX; ++q2){
                if (q2 < ncand){
                    float d = fmaf(-2.f, sacc[q2], cbn_s[cj[q2]]);
                    if (d < bdx || (d == bdx && cj[q2] < jf)){ bdx = d; jf = cj[q2]; }
                }
            }
        }
        g_idx[b*MT + m] = jf;
        atomicAdd(&g_counts[jf], 1);
    }
}

// ---------------- kernel 2: gather + straight-through out + commit partial ----------------
__global__ __launch_bounds__(256)
void k_out(const float* __restrict__ x, const float* __restrict__ cb, float* __restrict__ out){
    __shared__ int   idxs[MT];
    __shared__ float qt[MT*36];
    __shared__ float wred[8];
    const int tid = threadIdx.x;
    const int b = blockIdx.x, n = b >> 4, t0 = (b & 15) * MT;
    const float* xblk = x + (size_t)n*CD*TD + t0;
    float* outblk     = out + (size_t)n*CD*TD + t0;

    if (tid < MT) idxs[tid] = g_idx[b*MT + tid];
    __syncthreads();

    float csum = 0.f;
    for (int cc = 0; cc < 16; ++cc){            // chunks of 32 c
        __syncthreads();
        #pragma unroll
        for (int it = 0; it < 4; ++it){
            int i = tid + it*256;               // 0..1023 float4s
            int t = i >> 3, c4 = i & 7;
            float4 v = *(const float4*)(cb + (size_t)idxs[t]*CD + cc*32 + c4*4);
            *(float4*)&qt[t*36 + c4*4] = v;
        }
        __syncthreads();
        {
            int t = tid & 127, h = tid >> 7;
            #pragma unroll
            for (int cl = 0; cl < 16; ++cl){
                int c = h*16 + cl;
                float q  = qt[t*36 + c];
                float xv = xblk[(size_t)(cc*32 + c)*TD + t];
                outblk[(size_t)(cc*32 + c)*TD + t] = __fadd_rn(xv, __fsub_rn(q, xv));
                float df = __fsub_rn(xv, q);
                csum = fmaf(df, df, csum);
            }
        }
    }
    #pragma unroll
    for (int o = 16; o; o >>= 1) csum += __shfl_xor_sync(~0u, csum, o);
    __syncthreads();
    if ((tid & 31) == 0) wred[tid >> 5] = csum;
    __syncthreads();
    if (tid == 0){
        float s = 0.f;
        #pragma unroll
        for (int w = 0; w < 8; ++w) s += wred[w];
        g_partials[b] = s;
    }
}

// ---------------- kernel 3: finalize commit loss + perplexity ----------------
__global__ void k_final(float* __restrict__ out){
    __shared__ double sd[256];
    int tid = threadIdx.x;
    double s = 0.0;
    for (int i = tid; i < NTILE; i += 256) s += (double)g_partials[i];
    sd[tid] = s; __syncthreads();
    for (int o = 128; o; o >>= 1){ if (tid < o) sd[tid] += sd[tid + o]; __syncthreads(); }
    double commit = sd[0] / ((double)NT * (double)CD);
    __syncthreads();
    double e = 0.0;
    for (int i = tid; i < NB; i += 256){
        double p = (double)g_counts[i] / (double)NT;
        e += p * log(p + 1e-7);
    }
    sd[tid] = e; __syncthreads();
    for (int o = 128; o; o >>= 1){ if (tid < o) sd[tid] += sd[tid + o]; __syncthreads(); }
    if (tid == 0){
        out[(size_t)NN*CD*TD]     = (float)commit;
        out[(size_t)NN*CD*TD + 1] = (float)exp(-sd[0]);
    }
}

extern "C" void kernel_launch(void* const* d_in, const int* in_sizes, int n_in,
                              void* d_out, int out_size){
    const float* x  = (const float*)d_in[0];   // (32, 512, 2048) fp32
    const float* cb = (const float*)d_in[1];   // (1024, 512) fp32
    float* out = (float*)d_out;

    cudaFuncSetAttribute(k_main, cudaFuncAttributeMaxDynamicSharedMemorySize, SMTOT);

    k_norms<<<NB, 128>>>(cb);
    k_main<<<NTILE, 256, SMTOT>>>(x, cb);
    k_out<<<NTILE, 256>>>(x, cb, out);
    k_final<<<1, 256>>>(out);
}

// round 6
// speedup vs baseline: 4.5069x; 1.1440x over previous
#include <cuda_runtime.h>
#include <cuda_bf16.h>
#include <cstdint>

#define NB   1024
#define CD   512
#define NN   32
#define TD   2048
#define NT   (NN*TD)      // 65536 rows
#define MT   128          // rows per CTA
#define NTILE (NT/MT)     // 512 CTAs
#define NTHR 512
#define PASSES 8
#define PN   128          // codes per pass
#define KC   128          // k per chunk
#define NCH  4            // chunks per pass
#define CHT  (PASSES*NCH) // 32 chunks total
#define MARGIN 1.5f
#define CMAX 8

typedef unsigned long long ull;

__device__ __align__(16) __nv_bfloat16 g_cb16[NB*CD];
__device__ float g_cbnorm[NB];
__device__ int   g_counts[NB];
__device__ float g_partials[NTILE];

// smem map (bytes): A 128x512 bf16 swizzled @0 (131072; later qt staging),
// B 2x32768 @131072 (later cand 64KB), cbn @196608 (4096), sidx @200704 (512), wred @201216
#define SA    0
#define SB    131072
#define SCBN  196608
#define SIDX  200704
#define SWRED 201216
#define SMTOT 201344

static __device__ __forceinline__ uint32_t smem_u32(const void* p){
    uint32_t a; asm("{ .reg .u64 t; cvta.to.shared.u64 t, %1; cvt.u32.u64 %0, t; }" : "=r"(a) : "l"(p));
    return a;
}
static __device__ __forceinline__ uint32_t A_off(int r, int c){
    int ck = c >> 3;
    int cks = (ck & ~7) | ((ck ^ r) & 7);
    return (uint32_t)(r*1024 + cks*16 + (c&7)*2);
}
static __device__ __forceinline__ uint32_t B_off(int j, int kk){
    int ck = kk >> 3;
    int cks = (ck & 8) | ((ck ^ j) & 7);
    return (uint32_t)(j*256 + cks*16 + (kk&7)*2);
}
static __device__ __forceinline__ void ldsm4(uint32_t* r, uint32_t addr){
    asm volatile("ldmatrix.sync.aligned.m8n8.x4.shared.b16 {%0,%1,%2,%3}, [%4];"
        : "=r"(r[0]), "=r"(r[1]), "=r"(r[2]), "=r"(r[3]) : "r"(addr));
}
static __device__ __forceinline__ void mma16816(float* c, const uint32_t* a, uint32_t b0, uint32_t b1){
    asm volatile("mma.sync.aligned.m16n8k16.row.col.f32.bf16.bf16.f32 "
        "{%0,%1,%2,%3}, {%4,%5,%6,%7}, {%8,%9}, {%0,%1,%2,%3};"
        : "+f"(c[0]), "+f"(c[1]), "+f"(c[2]), "+f"(c[3])
        : "r"(a[0]), "r"(a[1]), "r"(a[2]), "r"(a[3]), "r"(b0), "r"(b1));
}

// ---------------- kernel 0: codebook norms + bf16 convert + zero counts ----------------
__global__ void k_norms(const float* __restrict__ cb){
    int j = blockIdx.x;
    float s = 0.f;
    for (int c = threadIdx.x; c < CD; c += 128){
        float v = cb[(size_t)j*CD + c];
        g_cb16[(size_t)j*CD + c] = __float2bfloat16(v);
        s = fmaf(v, v, s);
    }
    #pragma unroll
    for (int o = 16; o; o >>= 1) s += __shfl_xor_sync(~0u, s, o);
    __shared__ float ws[4];
    if ((threadIdx.x & 31) == 0) ws[threadIdx.x >> 5] = s;
    __syncthreads();
    if (threadIdx.x == 0){
        g_cbnorm[j] = (ws[0] + ws[1]) + (ws[2] + ws[3]);
        g_counts[j] = 0;
    }
}

// ---------------- B chunk stage via cp.async (512 threads) ----------------
static __device__ __forceinline__ void issueB(int q, int tid, uint32_t sbase){
    int p = q >> 2, kc = q & 3;
    const __nv_bfloat16* src0 = g_cb16 + (size_t)p*PN*CD + kc*KC;
    uint32_t bufb = sbase + SB + (uint32_t)(q & 1)*32768u;
    #pragma unroll
    for (int it = 0; it < 4; ++it){
        int idx = tid + it*NTHR;              // 0..2047 16B units
        int j = idx >> 4, ck = idx & 15;
        uint32_t dst = bufb + (uint32_t)(j*256 + (((ck & 8) | ((ck ^ j) & 7)) << 4));
        const void* srcp = (const void*)(src0 + (size_t)j*CD + ck*8);
        asm volatile("cp.async.cg.shared.global [%0], [%1], 16;" :: "r"(dst), "l"(srcp));
    }
    asm volatile("cp.async.commit_group;");
}

// ---------------- kernel 1: fused bf16 GEMM + top2 + refine + output + commit ----------------
__global__ __launch_bounds__(NTHR, 1)
void k_main(const float* __restrict__ x, const float* __restrict__ cb, float* __restrict__ out){
    extern __shared__ char sm[];
    const uint32_t sbase = smem_u32(sm);
    const int tid = threadIdx.x;
    const int wid = tid >> 5, l = tid & 31;
    const int wm = wid >> 3, wn = wid & 7;        // 2 M-warps x 8 N-warps
    const int b = blockIdx.x, n = b >> 4, t0 = (b & 15) * MT;
    const float* xblk = x + (size_t)n*CD*TD + t0;
    float* outblk     = out + (size_t)n*CD*TD + t0;
    float* cbn_s = (float*)(sm + SCBN);
    int*   sidx  = (int*)(sm + SIDX);
    float* wred  = (float*)(sm + SWRED);

    for (int i = tid; i < NB; i += NTHR) cbn_s[i] = g_cbnorm[i];

    // ---- stage A: x tile -> bf16, swizzled [t][c] ----
    #pragma unroll 4
    for (int it = 0; it < 64; ++it){
        int idx = tid + it*NTHR;
        int t = idx & 127, c = (idx >> 7) * 2;
        float v0 = xblk[(size_t)c*TD + t];
        float v1 = xblk[(size_t)(c+1)*TD + t];
        __nv_bfloat162 pk = __floats2bfloat162_rn(v0, v1);
        *(__nv_bfloat162*)(sm + SA + A_off(t, c)) = pk;
    }
    __syncthreads();

    issueB(0, tid, sbase);

    float bd[8][2]; int bj[8][2];
    #pragma unroll
    for (int r = 0; r < 8; ++r){
        bd[r][0] = bd[r][1] = 3.4e38f; bj[r][0] = bj[r][1] = 0;
    }

    const int arow = wm*64 + ((l >> 3) & 1)*8 + (l & 7);
    const int brow = wn*16 + (l >> 4)*8 + (l & 7);

    for (int p = 0; p < PASSES; ++p){
        float acc[4][2][4];
        #pragma unroll
        for (int ti = 0; ti < 4; ++ti)
            #pragma unroll
            for (int tj = 0; tj < 2; ++tj)
                #pragma unroll
                for (int e = 0; e < 4; ++e) acc[ti][tj][e] = 0.f;

        for (int kc = 0; kc < NCH; ++kc){
            int q = p*NCH + kc;
            if (q + 1 < CHT){ issueB(q + 1, tid, sbase); asm volatile("cp.async.wait_group 1;"); }
            else            { asm volatile("cp.async.wait_group 0;"); }
            __syncthreads();
            uint32_t bufb = sbase + SB + (uint32_t)(q & 1)*32768u;

            #pragma unroll
            for (int ks = 0; ks < 8; ++ks){
                const int acol = kc*KC + ks*16 + (l >> 4)*8;
                const int bcol = ks*16 + ((l >> 3) & 1)*8;
                uint32_t a[4][4], bf[4];
                #pragma unroll
                for (int ti = 0; ti < 4; ++ti)
                    ldsm4(a[ti], sbase + SA + A_off(arow + ti*16, acol));
                ldsm4(bf, bufb + B_off(brow, bcol));
                #pragma unroll
                for (int ti = 0; ti < 4; ++ti)
                    #pragma unroll
                    for (int tj = 0; tj < 2; ++tj)
                        mma16816(acc[ti][tj], a[ti], bf[tj*2], bf[tj*2+1]);
            }
            __syncthreads();
        }
        // ---- pass epilogue: distances -> per-(row-slot) top2 ----
        #pragma unroll
        for (int ti = 0; ti < 4; ++ti)
            #pragma unroll
            for (int tj = 0; tj < 2; ++tj)
                #pragma unroll
                for (int e = 0; e < 4; ++e){
                    int jg = p*PN + wn*16 + tj*8 + (l & 3)*2 + (e & 1);
                    float d = fmaf(-2.f, acc[ti][tj][e], cbn_s[jg]);
                    int r = ti*2 + (e >> 1);
                    if (d < bd[r][0]){
                        bd[r][1] = bd[r][0]; bj[r][1] = bj[r][0];
                        bd[r][0] = d;        bj[r][0] = jg;
                    } else if (d < bd[r][1]){
                        bd[r][1] = d;        bj[r][1] = jg;
                    }
                }
    }

    // ---- dump candidates (overlay B buffers): cand[128][64] of (d, j) ----
    float2* cand = (float2*)(sm + SB);
    #pragma unroll
    for (int r = 0; r < 8; ++r){
        int m = wm*64 + (r >> 1)*16 + (r & 1)*8 + (l >> 2);
        int slot = wn*8 + (l & 3)*2;
        cand[m*64 + slot + 0] = make_float2(bd[r][0], __int_as_float(bj[r][0]));
        cand[m*64 + slot + 1] = make_float2(bd[r][1], __int_as_float(bj[r][1]));
    }
    __syncthreads();

    // ---- per-row pick + exact fp32 refine if margin small ----
    if (tid < MT){
        int m = tid;
        float b1 = 3.4e38f; int j1 = 0x7fffffff;
        #pragma unroll 4
        for (int s = 0; s < 64; ++s){
            float2 e = cand[m*64 + s];
            int j = __float_as_int(e.y);
            if (e.x < b1 || (e.x == b1 && j < j1)){ b1 = e.x; j1 = j; }
        }
        int cj[CMAX]; int ncand = 0;
        #pragma unroll 4
        for (int s = 0; s < 64; ++s){
            float2 e = cand[m*64 + s];
            if (e.x <= b1 + MARGIN && ncand < CMAX) cj[ncand++] = __float_as_int(e.y);
        }
        int jf = j1;
        if (ncand > 1){
            float sacc[CMAX];
            const float* cps[CMAX];
            #pragma unroll
            for (int q2 = 0; q2 < CMAX; ++q2){
                sacc[q2] = 0.f;
                cps[q2] = cb + (size_t)cj[q2 < ncand ? q2 : 0]*CD;
            }
            const float* xr = xblk + m;
            #pragma unroll 4
            for (int c = 0; c < CD; ++c){
                float xv = xr[(size_t)c*TD];
                #pragma unroll
                for (int q2 = 0; q2 < CMAX; ++q2)
                    if (q2 < ncand) sacc[q2] = fmaf(xv, cps[q2][c], sacc[q2]);
            }
            float bdx = 3.4e38f; jf = 0x7fffffff;
            #pragma unroll
            for (int q2 = 0; q2 < CMAX; ++q2){
                if (q2 < ncand){
                    float d = fmaf(-2.f, sacc[q2], cbn_s[cj[q2]]);
                    if (d < bdx || (d == bdx && cj[q2] < jf)){ bdx = d; jf = cj[q2]; }
                }
            }
        }
        sidx[m] = jf;
        atomicAdd(&g_counts[jf], 1);
    }
    __syncthreads();

    // ---- fused output: gather q, straight-through write, commit partial ----
    float* qt = (float*)(sm + SA);              // 128 x 36 floats (A region retired)
    float csum = 0.f;
    for (int cc = 0; cc < 16; ++cc){            // chunks of 32 c
        __syncthreads();
        #pragma unroll
        for (int it = 0; it < 2; ++it){
            int i = tid + it*NTHR;              // 0..1023 float4s
            int t = i >> 3, c4 = i & 7;
            float4 v = *(const float4*)(cb + (size_t)sidx[t]*CD + cc*32 + c4*4);
            *(float4*)&qt[t*36 + c4*4] = v;
        }
        __syncthreads();
        {
            int t = tid & 127, h = tid >> 7;    // h in 0..3
            #pragma unroll
            for (int cl = 0; cl < 8; ++cl){
                int c = h*8 + cl;
                float q  = qt[t*36 + c];
                float xv = xblk[(size_t)(cc*32 + c)*TD + t];
                outblk[(size_t)(cc*32 + c)*TD + t] = __fadd_rn(xv, __fsub_rn(q, xv));
                float df = __fsub_rn(xv, q);
                csum = fmaf(df, df, csum);
            }
        }
    }
    #pragma unroll
    for (int o = 16; o; o >>= 1) csum += __shfl_xor_sync(~0u, csum, o);
    __syncthreads();
    if ((tid & 31) == 0) wred[tid >> 5] = csum;
    __syncthreads();
    if (tid == 0){
        float s = 0.f;
        #pragma unroll
        for (int w = 0; w < 16; ++w) s += wred[w];
        g_partials[b] = s;
    }
}

// ---------------- kernel 2: finalize commit loss + perplexity ----------------
__global__ void k_final(float* __restrict__ out){
    __shared__ double sd[256];
    int tid = threadIdx.x;
    double s = 0.0;
    for (int i = tid; i < NTILE; i += 256) s += (double)g_partials[i];
    sd[tid] = s; __syncthreads();
    for (int o = 128; o; o >>= 1){ if (tid < o) sd[tid] += sd[tid + o]; __syncthreads(); }
    double commit = sd[0] / ((double)NT * (double)CD);
    __syncthreads();
    double e = 0.0;
    for (int i = tid; i < NB; i += 256){
        double p = (double)g_counts[i] / (double)NT;
        e += p * log(p + 1e-7);
    }
    sd[tid] = e; __syncthreads();
    for (int o = 128; o; o >>= 1){ if (tid < o) sd[tid] += sd[tid + o]; __syncthreads(); }
    if (tid == 0){
        out[(size_t)NN*CD*TD]     = (float)commit;
        out[(size_t)NN*CD*TD + 1] = (float)exp(-sd[0]);
    }
}

extern "C" void kernel_launch(void* const* d_in, const int* in_sizes, int n_in,
                              void* d_out, int out_size){
    const float* x  = (const float*)d_in[0];   // (32, 512, 2048) fp32
    const float* cb = (const float*)d_in[1];   // (1024, 512) fp32
    float* out = (float*)d_out;

    cudaFuncSetAttribute(k_main, cudaFuncAttributeMaxDynamicSharedMemorySize, SMTOT);

    k_norms<<<NB, 128>>>(cb);
    k_main<<<NTILE, NTHR, SMTOT>>>(x, cb, out);
    k_final<<<1, 256>>>(out);
}